// round 1
// baseline (speedup 1.0000x reference)
#include <cuda_runtime.h>

#define BB 8
#define CC 64
#define WH 214272          // 496*432
#define BLOCKS_PER_BATCH 837  // WH / 256
#define EPSF 0.001f

// Scratch (device globals — no allocations allowed)
__device__ float         g_S1[CC];
__device__ float         g_S2[CC];
__device__ int           g_n[BB];
__device__ float         g_inv[CC];
__device__ int           g_write00[BB];
__device__ unsigned char g_mask[BB * WH];   // 1.7 MB

// ---------------------------------------------------------------------------
// Zero the accumulators (graph is replayed many times; must be deterministic)
// ---------------------------------------------------------------------------
__global__ void zero_kernel() {
    int t = threadIdx.x;
    if (t < CC) { g_S1[t] = 0.0f; g_S2[t] = 0.0f; }
    if (t < BB) g_n[t] = 0;
}

// ---------------------------------------------------------------------------
// Pass 1: fused mask + per-channel masked sums (single read of x).
// One thread = one spatial position, holds all 64 channel values in registers.
// ---------------------------------------------------------------------------
__global__ void __launch_bounds__(256) stats_kernel(const float* __restrict__ x) {
    const int tid  = threadIdx.x;
    const int b    = blockIdx.x / BLOCKS_PER_BATCH;
    const int pos  = (blockIdx.x % BLOCKS_PER_BATCH) * 256 + tid;
    const float* xb = x + (size_t)b * CC * WH + pos;

    float v[CC];
    float csum = 0.0f;
#pragma unroll
    for (int c = 0; c < CC; c++) {
        v[c] = xb[(size_t)c * WH];
        csum += v[c];
    }
    const bool m = (csum != 0.0f);
    g_mask[(size_t)b * WH + pos] = m ? 1 : 0;

    const int warp = tid >> 5;
    const int lane = tid & 31;
    const float mf = m ? 1.0f : 0.0f;

    __shared__ float sS1[8][CC];
    __shared__ float sS2[8][CC];
    __shared__ int   sCnt[8];

    unsigned ballot = __ballot_sync(0xffffffffu, m);
    if (lane == 0) sCnt[warp] = __popc(ballot);

#pragma unroll
    for (int c = 0; c < CC; c++) {
        float val = v[c] * mf;
        float s1 = val;
        float s2 = val * val;
#pragma unroll
        for (int o = 16; o > 0; o >>= 1) {
            s1 += __shfl_xor_sync(0xffffffffu, s1, o);
            s2 += __shfl_xor_sync(0xffffffffu, s2, o);
        }
        if (lane == 0) { sS1[warp][c] = s1; sS2[warp][c] = s2; }
    }
    __syncthreads();

    if (tid < CC) {
        float a1 = 0.0f, a2 = 0.0f;
#pragma unroll
        for (int w = 0; w < 8; w++) { a1 += sS1[w][tid]; a2 += sS2[w][tid]; }
        atomicAdd(&g_S1[tid], a1);
        atomicAdd(&g_S2[tid], a2);
    }
    if (tid == 0) {
        int cn = 0;
#pragma unroll
        for (int w = 0; w < 8; w++) cn += sCnt[w];
        atomicAdd(&g_n[b], cn);
    }
}

// ---------------------------------------------------------------------------
// Pass 2 (tiny): N, pad, write00, pad*x00 corrections, inv = rsqrt(var+eps)
// ---------------------------------------------------------------------------
__global__ void finalize_kernel(const float* __restrict__ x) {
    __shared__ int spad[BB];
    __shared__ int sN;
    const int t = threadIdx.x;
    if (t == 0) {
        int mx = 0;
#pragma unroll
        for (int b = 0; b < BB; b++) mx = max(mx, g_n[b]);
        sN = mx;
#pragma unroll
        for (int b = 0; b < BB; b++) {
            int p = mx - g_n[b];
            spad[b] = p;
            g_write00[b] = (p > 0) || (g_mask[(size_t)b * WH] != 0);
        }
    }
    __syncthreads();
    if (t < CC) {
        float s1 = g_S1[t];
        float s2 = g_S2[t];
#pragma unroll
        for (int b = 0; b < BB; b++) {
            float x00 = x[(size_t)b * CC * WH + (size_t)t * WH];
            float p = (float)spad[b];
            s1 += p * x00;
            s2 += p * x00 * x00;
        }
        float count = (float)BB * (float)sN;
        float mean = s1 / count;
        float var  = s2 / count - mean * mean;
        g_inv[t] = rsqrtf(var + EPSF);
    }
}

// ---------------------------------------------------------------------------
// Pass 3: normalize, float4 vectorized (read x + mask, write out)
// ---------------------------------------------------------------------------
__global__ void __launch_bounds__(256) norm_kernel(const float* __restrict__ x,
                                                   float* __restrict__ out) {
    const unsigned int i4 = blockIdx.x * 256u + threadIdx.x;
    const unsigned int i  = i4 * 4u;
    const unsigned int bc = i / WH;          // b*64 + c
    const unsigned int s  = i - bc * WH;     // spatial offset within (b,c) plane
    const unsigned int b  = bc >> 6;
    const unsigned int c  = bc & 63u;

    float4 v = reinterpret_cast<const float4*>(x)[i4];
    const float inv = g_inv[c];
    const unsigned int m4 =
        *reinterpret_cast<const unsigned int*>(g_mask + (size_t)b * WH + s);

    float4 o;
    o.x = (m4 & 0x000000ffu) ? v.x * inv : v.x;
    o.y = (m4 & 0x0000ff00u) ? v.y * inv : v.y;
    o.z = (m4 & 0x00ff0000u) ? v.z * inv : v.z;
    o.w = (m4 & 0xff000000u) ? v.w * inv : v.w;

    if (s == 0) {
        // write00 superset of mask00; when both false, x00==0 so value unchanged
        o.x = g_write00[b] ? v.x * inv : v.x;
    }
    reinterpret_cast<float4*>(out)[i4] = o;
}

// ---------------------------------------------------------------------------
extern "C" void kernel_launch(void* const* d_in, const int* in_sizes, int n_in,
                              void* d_out, int out_size) {
    const float* x = (const float*)d_in[0];
    float* out = (float*)d_out;

    zero_kernel<<<1, 64>>>();
    stats_kernel<<<BB * BLOCKS_PER_BATCH, 256>>>(x);
    finalize_kernel<<<1, 64>>>(x);
    const int total4 = (BB * CC * WH) / 4;          // 27,426,816
    norm_kernel<<<total4 / 256, 256>>>(x, out);     // 107,136 blocks
}

// round 2
// speedup vs baseline: 1.2816x; 1.2816x over previous
#include <cuda_runtime.h>

#define BB 8
#define CC 64
#define WH 214272             // 496*432
#define BLOCKS_PER_BATCH 837  // WH / 256
#define EPSF 0.001f

// Scratch (device globals — no allocations allowed)
__device__ float         g_S1[CC];
__device__ float         g_S2[CC];
__device__ int           g_n[BB];
__device__ float         g_inv[CC];
__device__ int           g_write00[BB];
__device__ unsigned char g_mask[BB * WH];   // 1.7 MB

// ---------------------------------------------------------------------------
// Zero the accumulators (graph is replayed many times; must be deterministic)
// ---------------------------------------------------------------------------
__global__ void zero_kernel() {
    int t = threadIdx.x;
    if (t < CC) { g_S1[t] = 0.0f; g_S2[t] = 0.0f; }
    if (t < BB) g_n[t] = 0;
}

// ---------------------------------------------------------------------------
// Pass 1: fused mask + per-channel masked sums (single read of x).
// One thread per spatial position loads all 64 channels (64-deep MLP,
// fully coalesced). Cross-thread per-channel reduction via a two-phase
// shared-memory transpose (plain LDS/FFMA) instead of 640 SHFLs/thread.
// ---------------------------------------------------------------------------
__global__ void __launch_bounds__(256) stats_kernel(const float* __restrict__ x) {
    const int tid  = threadIdx.x;
    const int b    = blockIdx.x / BLOCKS_PER_BATCH;
    const int pos  = (blockIdx.x % BLOCKS_PER_BATCH) * 256 + tid;
    const float* xb = x + (size_t)b * CC * WH + pos;

    float v[CC];
    float csum = 0.0f;
#pragma unroll
    for (int c = 0; c < CC; c++) {
        v[c] = xb[(size_t)c * WH];
        csum += v[c];
    }
    const bool  m  = (csum != 0.0f);
    const float mf = m ? 1.0f : 0.0f;
    g_mask[(size_t)b * WH + pos] = m ? 1 : 0;

    const int warp = tid >> 5;
    const int lane = tid & 31;

    __shared__ float sm[128 * 65];   // 33.3 KB transpose buffer (padded)
    __shared__ float r1[256];
    __shared__ float r2[256];
    __shared__ int   sCnt[8];

    unsigned ballot = __ballot_sync(0xffffffffu, m);
    if (lane == 0) sCnt[warp] = __popc(ballot);

    const int c = tid & 63;          // channel this thread reduces
    const int g = tid >> 6;          // position group (4 groups x 32 pos)
    float a1 = 0.0f, a2 = 0.0f;

#pragma unroll
    for (int phase = 0; phase < 2; phase++) {
        // half of the threads store their (masked) channel vector
        if ((tid >> 7) == phase) {
            const int row = tid & 127;
#pragma unroll
            for (int cc = 0; cc < CC; cc++) sm[row * 65 + cc] = v[cc] * mf;
        }
        __syncthreads();
        // all 256 threads reduce this half: 32 positions per (channel, group)
#pragma unroll
        for (int i = 0; i < 32; i++) {
            float val = sm[(g * 32 + i) * 65 + c];
            a1 += val;
            a2 += val * val;
        }
        __syncthreads();
    }

    r1[tid] = a1;
    r2[tid] = a2;
    __syncthreads();

    if (tid < CC) {
        float s1 = r1[tid] + r1[tid + 64] + r1[tid + 128] + r1[tid + 192];
        float s2 = r2[tid] + r2[tid + 64] + r2[tid + 128] + r2[tid + 192];
        atomicAdd(&g_S1[tid], s1);
        atomicAdd(&g_S2[tid], s2);
    }
    if (tid == 0) {
        int cn = 0;
#pragma unroll
        for (int w = 0; w < 8; w++) cn += sCnt[w];
        atomicAdd(&g_n[b], cn);
    }
}

// ---------------------------------------------------------------------------
// Pass 2 (tiny): N, pad, write00, pad*x00 corrections, inv = rsqrt(var+eps)
// ---------------------------------------------------------------------------
__global__ void finalize_kernel(const float* __restrict__ x) {
    __shared__ int spad[BB];
    __shared__ int sN;
    const int t = threadIdx.x;
    if (t == 0) {
        int mx = 0;
#pragma unroll
        for (int b = 0; b < BB; b++) mx = max(mx, g_n[b]);
        sN = mx;
#pragma unroll
        for (int b = 0; b < BB; b++) {
            int p = mx - g_n[b];
            spad[b] = p;
            g_write00[b] = (p > 0) || (g_mask[(size_t)b * WH] != 0);
        }
    }
    __syncthreads();
    if (t < CC) {
        float s1 = g_S1[t];
        float s2 = g_S2[t];
#pragma unroll
        for (int b = 0; b < BB; b++) {
            float x00 = x[(size_t)b * CC * WH + (size_t)t * WH];
            float p = (float)spad[b];
            s1 += p * x00;
            s2 += p * x00 * x00;
        }
        float count = (float)BB * (float)sN;
        float mean = s1 / count;
        float var  = s2 / count - mean * mean;
        g_inv[t] = rsqrtf(var + EPSF);
    }
}

// ---------------------------------------------------------------------------
// Pass 3: normalize, float4 vectorized (read x + mask, write out)
// Already at 80.8% of DRAM spec — left structurally unchanged.
// ---------------------------------------------------------------------------
__global__ void __launch_bounds__(256) norm_kernel(const float* __restrict__ x,
                                                   float* __restrict__ out) {
    const unsigned int i4 = blockIdx.x * 256u + threadIdx.x;
    const unsigned int i  = i4 * 4u;
    const unsigned int bc = i / WH;          // b*64 + c
    const unsigned int s  = i - bc * WH;     // spatial offset within (b,c) plane
    const unsigned int b  = bc >> 6;
    const unsigned int c  = bc & 63u;

    float4 v = reinterpret_cast<const float4*>(x)[i4];
    const float inv = g_inv[c];
    const unsigned int m4 =
        *reinterpret_cast<const unsigned int*>(g_mask + (size_t)b * WH + s);

    float4 o;
    o.x = (m4 & 0x000000ffu) ? v.x * inv : v.x;
    o.y = (m4 & 0x0000ff00u) ? v.y * inv : v.y;
    o.z = (m4 & 0x00ff0000u) ? v.z * inv : v.z;
    o.w = (m4 & 0xff000000u) ? v.w * inv : v.w;

    if (s == 0) {
        // write00 superset of mask00; when both false, x00==0 so value unchanged
        o.x = g_write00[b] ? v.x * inv : v.x;
    }
    reinterpret_cast<float4*>(out)[i4] = o;
}

// ---------------------------------------------------------------------------
extern "C" void kernel_launch(void* const* d_in, const int* in_sizes, int n_in,
                              void* d_out, int out_size) {
    const float* x = (const float*)d_in[0];
    float* out = (float*)d_out;

    zero_kernel<<<1, 64>>>();
    stats_kernel<<<BB * BLOCKS_PER_BATCH, 256>>>(x);
    finalize_kernel<<<1, 64>>>(x);
    const int total4 = (BB * CC * WH) / 4;          // 27,426,816
    norm_kernel<<<total4 / 256, 256>>>(x, out);     // 107,136 blocks
}

// round 3
// speedup vs baseline: 1.4191x; 1.1073x over previous
#include <cuda_runtime.h>

#define BB 8
#define CC 64
#define WH 214272             // 496*432
#define WH4 53568             // WH/4
#define BLOCKS_PER_BATCH 837  // WH / 256
#define EPSF 0.001f

// Scratch (device globals — no allocations allowed).
// Zero-initialized at module load; finalize_kernel resets them after use so
// every graph replay starts from a clean state (no separate zero kernel).
__device__ float         g_S1[CC];
__device__ float         g_S2[CC];
__device__ int           g_n[BB];
__device__ float         g_inv[CC];
__device__ int           g_write00[BB];
__device__ unsigned char g_mask[BB * WH];   // 1.7 MB

// ---------------------------------------------------------------------------
// Pass 1: fused mask + per-channel masked sums (single read of x).
// One thread per spatial position loads all 64 channels (64-deep MLP,
// fully coalesced). Cross-thread per-channel reduction via a two-phase
// shared-memory transpose (plain LDS/FFMA).
// ---------------------------------------------------------------------------
__global__ void __launch_bounds__(256) stats_kernel(const float* __restrict__ x) {
    const int tid  = threadIdx.x;
    const int b    = blockIdx.x / BLOCKS_PER_BATCH;
    const int pos  = (blockIdx.x % BLOCKS_PER_BATCH) * 256 + tid;
    const float* xb = x + (size_t)b * CC * WH + pos;

    float v[CC];
    float csum = 0.0f;
#pragma unroll
    for (int c = 0; c < CC; c++) {
        v[c] = xb[(size_t)c * WH];
        csum += v[c];
    }
    const bool  m  = (csum != 0.0f);
    const float mf = m ? 1.0f : 0.0f;
    g_mask[(size_t)b * WH + pos] = m ? 1 : 0;

    const int warp = tid >> 5;
    const int lane = tid & 31;

    __shared__ float sm[128 * 65];   // 33.3 KB transpose buffer (padded)
    __shared__ float r1[256];
    __shared__ float r2[256];
    __shared__ int   sCnt[8];

    unsigned ballot = __ballot_sync(0xffffffffu, m);
    if (lane == 0) sCnt[warp] = __popc(ballot);

    const int c = tid & 63;          // channel this thread reduces
    const int g = tid >> 6;          // position group (4 groups x 32 pos)
    float a1 = 0.0f, a2 = 0.0f;

#pragma unroll
    for (int phase = 0; phase < 2; phase++) {
        // half of the threads store their (masked) channel vector
        if ((tid >> 7) == phase) {
            const int row = tid & 127;
#pragma unroll
            for (int cc = 0; cc < CC; cc++) sm[row * 65 + cc] = v[cc] * mf;
        }
        __syncthreads();
        // all 256 threads reduce this half: 32 positions per (channel, group)
#pragma unroll
        for (int i = 0; i < 32; i++) {
            float val = sm[(g * 32 + i) * 65 + c];
            a1 += val;
            a2 += val * val;
        }
        __syncthreads();
    }

    r1[tid] = a1;
    r2[tid] = a2;
    __syncthreads();

    if (tid < CC) {
        float s1 = r1[tid] + r1[tid + 64] + r1[tid + 128] + r1[tid + 192];
        float s2 = r2[tid] + r2[tid + 64] + r2[tid + 128] + r2[tid + 192];
        atomicAdd(&g_S1[tid], s1);
        atomicAdd(&g_S2[tid], s2);
    }
    if (tid == 0) {
        int cn = 0;
#pragma unroll
        for (int w = 0; w < 8; w++) cn += sCnt[w];
        atomicAdd(&g_n[b], cn);
    }
}

// ---------------------------------------------------------------------------
// Pass 2 (tiny): N, pad, write00, pad*x00 corrections, inv = rsqrt(var+eps).
// Also RESETS the accumulators for the next graph replay.
// ---------------------------------------------------------------------------
__global__ void finalize_kernel(const float* __restrict__ x) {
    __shared__ int spad[BB];
    __shared__ int sN;
    const int t = threadIdx.x;
    if (t == 0) {
        int mx = 0;
#pragma unroll
        for (int b = 0; b < BB; b++) mx = max(mx, g_n[b]);
        sN = mx;
#pragma unroll
        for (int b = 0; b < BB; b++) {
            int p = mx - g_n[b];
            spad[b] = p;
            g_write00[b] = (p > 0) || (g_mask[(size_t)b * WH] != 0);
        }
    }
    __syncthreads();
    if (t < CC) {
        float s1 = g_S1[t];
        float s2 = g_S2[t];
#pragma unroll
        for (int b = 0; b < BB; b++) {
            float x00 = x[(size_t)b * CC * WH + (size_t)t * WH];
            float p = (float)spad[b];
            s1 += p * x00;
            s2 += p * x00 * x00;
        }
        float count = (float)BB * (float)sN;
        float mean = s1 / count;
        float var  = s2 / count - mean * mean;
        g_inv[t] = rsqrtf(var + EPSF);
        // reset for next replay (t==0's reads of g_n happened before the barrier)
        g_S1[t] = 0.0f;
        g_S2[t] = 0.0f;
    }
    if (t < BB) g_n[t] = 0;
}

// ---------------------------------------------------------------------------
// Pass 3: normalize, float4 vectorized.
// Plane (b,c) comes from blockIdx.y -> no integer division, inv is a
// block-uniform load, per-thread index math is a single IMAD.
// ---------------------------------------------------------------------------
__global__ void __launch_bounds__(256) norm_kernel(const float* __restrict__ x,
                                                   float* __restrict__ out) {
    const unsigned int bc = blockIdx.y;       // b*64 + c  (0..511)
    const unsigned int b  = bc >> 6;
    const unsigned int c  = bc & 63u;
    const unsigned int p4 = blockIdx.x * 256u + threadIdx.x;  // float4 idx in plane
    if (p4 >= WH4) return;

    const size_t i4 = (size_t)bc * WH4 + p4;
    float4 v = reinterpret_cast<const float4*>(x)[i4];
    const float inv = g_inv[c];
    const unsigned int s = p4 * 4u;
    const unsigned int m4 =
        *reinterpret_cast<const unsigned int*>(g_mask + (size_t)b * WH + s);

    float4 o;
    o.x = (m4 & 0x000000ffu) ? v.x * inv : v.x;
    o.y = (m4 & 0x0000ff00u) ? v.y * inv : v.y;
    o.z = (m4 & 0x00ff0000u) ? v.z * inv : v.z;
    o.w = (m4 & 0xff000000u) ? v.w * inv : v.w;

    if (s == 0) {
        // write00 superset of mask00; when both false, x00==0 so value unchanged
        o.x = g_write00[b] ? v.x * inv : v.x;
    }
    reinterpret_cast<float4*>(out)[i4] = o;
}

// ---------------------------------------------------------------------------
extern "C" void kernel_launch(void* const* d_in, const int* in_sizes, int n_in,
                              void* d_out, int out_size) {
    const float* x = (const float*)d_in[0];
    float* out = (float*)d_out;

    stats_kernel<<<BB * BLOCKS_PER_BATCH, 256>>>(x);
    finalize_kernel<<<1, 64>>>(x);
    dim3 ngrid((WH4 + 255) / 256, BB * CC);   // (210, 512)
    norm_kernel<<<ngrid, 256>>>(x, out);
}

// round 4
// speedup vs baseline: 1.4366x; 1.0123x over previous
#include <cuda_runtime.h>

#define BB 8
#define CC 64
#define WH 214272             // 496*432
#define WH4 53568             // WH/4
#define BLOCKS_PER_BATCH 837  // WH / 256
#define NBLOCKS (BB * BLOCKS_PER_BATCH)
#define EPSF 0.001f

// Scratch (device globals — no allocations allowed).
// Zero-initialized at module load; the merged finalize tail resets them after
// consuming, so every graph replay starts from a clean state.
__device__ float        g_S1[CC];
__device__ float        g_S2[CC];
__device__ int          g_n[BB];
__device__ float        g_inv[CC];
__device__ unsigned int g_done;

// ---------------------------------------------------------------------------
// Pass 1: per-channel sums + per-batch nonzero-position count (single read).
// Key simplification: unmasked positions have x == 0 in every channel, so the
// masked per-channel sums equal the PLAIN per-channel sums; no mask array and
// no masking multiply are needed. Only n[b] still uses the predicate (ballot).
// The last block to finish runs the finalize step inline (no extra launch).
// ---------------------------------------------------------------------------
__global__ void __launch_bounds__(256) stats_kernel(const float* __restrict__ x) {
    const int tid  = threadIdx.x;
    const int b    = blockIdx.x / BLOCKS_PER_BATCH;
    const int pos  = (blockIdx.x % BLOCKS_PER_BATCH) * 256 + tid;
    const float* xb = x + (size_t)b * CC * WH + pos;

    float v[CC];
    float csum = 0.0f;
#pragma unroll
    for (int c = 0; c < CC; c++) {
        v[c] = __ldcs(&xb[(size_t)c * WH]);   // streaming: no reuse before norm
        csum += v[c];
    }
    const bool m = (csum != 0.0f);

    const int warp = tid >> 5;
    const int lane = tid & 31;

    __shared__ float sm[128 * 65];   // 33.3 KB transpose buffer (padded)
    __shared__ float r1[256];
    __shared__ float r2[256];
    __shared__ int   sCnt[8];

    unsigned ballot = __ballot_sync(0xffffffffu, m);
    if (lane == 0) sCnt[warp] = __popc(ballot);

    const int c = tid & 63;          // channel this thread reduces
    const int g = tid >> 6;          // position group (4 groups x 32 pos)
    float a1 = 0.0f, a2 = 0.0f;

#pragma unroll
    for (int phase = 0; phase < 2; phase++) {
        if ((tid >> 7) == phase) {
            const int row = tid & 127;
#pragma unroll
            for (int cc = 0; cc < CC; cc++) sm[row * 65 + cc] = v[cc];
        }
        __syncthreads();
#pragma unroll
        for (int i = 0; i < 32; i++) {
            float val = sm[(g * 32 + i) * 65 + c];
            a1 += val;
            a2 += val * val;
        }
        __syncthreads();
    }

    r1[tid] = a1;
    r2[tid] = a2;
    __syncthreads();

    if (tid < CC) {
        float s1 = r1[tid] + r1[tid + 64] + r1[tid + 128] + r1[tid + 192];
        float s2 = r2[tid] + r2[tid + 64] + r2[tid + 128] + r2[tid + 192];
        atomicAdd(&g_S1[tid], s1);
        atomicAdd(&g_S2[tid], s2);
    }
    if (tid == 0) {
        int cn = 0;
#pragma unroll
        for (int w = 0; w < 8; w++) cn += sCnt[w];
        atomicAdd(&g_n[b], cn);
    }

    // ---- merged finalize: last block to arrive computes inv + resets state --
    __shared__ bool isLast;
    __shared__ int  spad[BB];
    __shared__ int  sN;
    __threadfence();
    if (tid == 0) {
        unsigned int d = atomicAdd(&g_done, 1u);
        isLast = (d == (unsigned int)(NBLOCKS - 1));
    }
    __syncthreads();
    if (!isLast) return;

    if (tid == 0) {
        g_done = 0;
        int mx = 0;
#pragma unroll
        for (int bb = 0; bb < BB; bb++) mx = max(mx, g_n[bb]);
        sN = mx;
#pragma unroll
        for (int bb = 0; bb < BB; bb++) {
            spad[bb] = mx - g_n[bb];
            g_n[bb] = 0;
        }
    }
    __syncthreads();
    if (tid < CC) {
        float s1 = g_S1[tid];
        float s2 = g_S2[tid];
#pragma unroll
        for (int bb = 0; bb < BB; bb++) {
            float x00 = x[(size_t)bb * CC * WH + (size_t)tid * WH];
            float p = (float)spad[bb];
            s1 += p * x00;
            s2 += p * x00 * x00;
        }
        float count = (float)BB * (float)sN;
        float mean = s1 / count;
        float var  = s2 / count - mean * mean;
        g_inv[tid] = rsqrtf(var + EPSF);
        g_S1[tid] = 0.0f;
        g_S2[tid] = 0.0f;
    }
}

// ---------------------------------------------------------------------------
// Pass 2: normalize = pure scale stream. out = x * inv[c] everywhere:
// unmasked positions have x == 0 (0*inv == 0 == passthrough), and the (0,0)
// special case also reduces to x00*inv in all reachable states.
// ---------------------------------------------------------------------------
__global__ void __launch_bounds__(256) norm_kernel(const float* __restrict__ x,
                                                   float* __restrict__ out) {
    const unsigned int bc = blockIdx.y;       // b*64 + c  (0..511)
    const unsigned int c  = bc & 63u;
    const unsigned int p4 = blockIdx.x * 256u + threadIdx.x;
    if (p4 >= WH4) return;

    const size_t i4 = (size_t)bc * WH4 + p4;
    const float inv = g_inv[c];
    float4 v = __ldcs(reinterpret_cast<const float4*>(x) + i4);
    float4 o;
    o.x = v.x * inv;
    o.y = v.y * inv;
    o.z = v.z * inv;
    o.w = v.w * inv;
    __stcs(reinterpret_cast<float4*>(out) + i4, o);
}

// ---------------------------------------------------------------------------
extern "C" void kernel_launch(void* const* d_in, const int* in_sizes, int n_in,
                              void* d_out, int out_size) {
    const float* x = (const float*)d_in[0];
    float* out = (float*)d_out;

    stats_kernel<<<NBLOCKS, 256>>>(x);
    dim3 ngrid((WH4 + 255) / 256, BB * CC);   // (210, 512)
    norm_kernel<<<ngrid, 256>>>(x, out);
}